// round 4
// baseline (speedup 1.0000x reference)
#include <cuda_runtime.h>
#include <math.h>

// fp32 results of the two big reductions: [0..15] embf, [16..31] squ_sum
__device__ float g_accf[32];

// Emulate XLA-CPU's strength-reduced matvec: per output column e, a single
// fp32 accumulator summed sequentially over f = 0..F-1 (bit-faithful to a
// single-accumulator sequential loop, FMA-contracted as fast-math emits).
// One block per e; lane 0 owns both chains (embf and squ) so loads are shared.
__global__ void serial_chain_kernel(const float* __restrict__ x,
                                    const float* __restrict__ emb,
                                    int F) {
    if (threadIdx.x != 0) return;
    const int e = blockIdx.x;                 // 0..15
    const float* __restrict__ p = emb + e;    // column e, stride 16

    float acc1 = 0.0f;   // embf_e    = sum_f emb[f,e] * x[f]
    float acc2 = 0.0f;   // squ_e     = sum_f (emb[f,e]^2) * (x[f]^2)

    long fp = 0;
    #pragma unroll 8
    for (int f = 0; f < F; ++f, fp += 16) {
        float v  = __ldg(p + fp);
        float xv = __ldg(x + f);
        acc1 = fmaf(v, xv, acc1);
        float v2 = v * v;      // rounded fp32 (emb*emb materialized by ref)
        float x2 = xv * xv;    // rounded fp32 (x*x materialized by ref)
        acc2 = fmaf(v2, x2, acc2);
    }

    g_accf[e]      = acc1;
    g_accf[16 + e] = acc2;
}

// Tail: logistic + FM + 2-layer MLP + sigmoid. 1 block, 32 threads, fp32.
// Dots here are 16/32/49 terms; rounding ~1e-7, far under threshold.
__global__ void tail_kernel(const float* __restrict__ w_log,   // (1,16)
                            const float* __restrict__ b_log,   // (1,)
                            const float* __restrict__ w1,      // (32,16)
                            const float* __restrict__ b1,      // (32,)
                            const float* __restrict__ w2,      // (32,32)
                            const float* __restrict__ b2,      // (32,)
                            const float* __restrict__ w_out,   // (1,49)
                            const float* __restrict__ b_out,   // (1,)
                            float* __restrict__ out) {
    __shared__ float s_h1[32];
    __shared__ float s_embf[16];
    int t = threadIdx.x;

    if (t < 16) s_embf[t] = g_accf[t];
    __syncwarp();

    // h1 = relu(embf @ w1^T + b1); sequential over e ascending
    float h1 = b1[t];
    #pragma unroll
    for (int e = 0; e < 16; e++) h1 = fmaf(s_embf[e], w1[t * 16 + e], h1);
    h1 = fmaxf(h1, 0.0f);
    s_h1[t] = h1;
    __syncwarp();

    // h2 = relu(h1 @ w2^T + b2)
    float h2 = b2[t];
    #pragma unroll
    for (int k = 0; k < 32; k++) h2 = fmaf(s_h1[k], w2[t * 32 + k], h2);
    h2 = fmaxf(h2, 0.0f);

    // concat = [h2 (32), fm (16), logistic (1)] . w_out + b_out
    float part = h2 * w_out[t];
    if (t < 16) {
        float ef = s_embf[t];
        float fm = 0.5f * (ef * ef - g_accf[16 + t]);
        part = fmaf(fm, w_out[32 + t], part);
    }
    if (t == 0) {
        float logit = b_log[0];
        #pragma unroll
        for (int e = 0; e < 16; e++) logit = fmaf(s_embf[e], w_log[e], logit);
        part = fmaf(logit, w_out[48], part);
        part += b_out[0];
    }

    #pragma unroll
    for (int off = 16; off > 0; off >>= 1)
        part += __shfl_down_sync(0xffffffffu, part, off);

    if (t == 0) out[0] = 1.0f / (1.0f + expf(-part));
}

extern "C" void kernel_launch(void* const* d_in, const int* in_sizes, int n_in,
                              void* d_out, int out_size) {
    const float* x     = (const float*)d_in[0];
    const float* emb   = (const float*)d_in[1];
    const float* w_log = (const float*)d_in[2];
    const float* b_log = (const float*)d_in[3];
    const float* w1    = (const float*)d_in[4];
    const float* b1    = (const float*)d_in[5];
    const float* w2    = (const float*)d_in[6];
    const float* b2    = (const float*)d_in[7];
    const float* w_out = (const float*)d_in[8];
    const float* b_out = (const float*)d_in[9];
    float* out = (float*)d_out;

    int F = in_sizes[0];   // 2,000,000

    serial_chain_kernel<<<16, 32>>>(x, emb, F);
    tail_kernel<<<1, 32>>>(w_log, b_log, w1, b1, w2, b2, w_out, b_out, out);
}

// round 5
// speedup vs baseline: 12.9056x; 12.9056x over previous
#include <cuda_runtime.h>
#include <math.h>

// fp32 results of the two big reductions: [0..15] embf, [16..31] squ_sum
__device__ float g_accf[32];

#define TILE 2048
#define NPROD 128   // producer threads (warps 1..4)

// One block per output column e. Producer warps compute the per-term products
// (rounding of products is order-independent); consumer lanes replay the
// reference's sequential fp32 add chain from shared memory.
__global__ void __launch_bounds__(160, 1)
serial_chain_kernel(const float* __restrict__ x,
                    const float* __restrict__ emb,
                    int F) {
    __shared__ float s_t[2][2][TILE];   // [stage][chain][i]

    const int e   = blockIdx.x;     // 0..15
    const int tid = threadIdx.x;
    const int ntiles = (F + TILE - 1) / TILE;

    // ---- prologue: producers fill tile 0 into stage 0 ----
    if (tid >= 32) {
        const int p = tid - 32;     // 0..127
        #pragma unroll
        for (int k = 0; k < TILE / NPROD; k++) {
            int i = p + k * NPROD;
            if (i < F) {
                float v  = __ldg(emb + (long)i * 16 + e);
                float xv = __ldg(x + i);
                s_t[0][0][i] = __fmul_rn(v, xv);
                s_t[0][1][i] = __fmul_rn(__fmul_rn(v, v), __fmul_rn(xv, xv));
            }
        }
    }
    __syncthreads();

    float acc = 0.0f;   // lane 0: embf chain, lane 1: squ chain

    for (int t = 0; t < ntiles; t++) {
        const int cur = t & 1;

        if (tid >= 32) {
            // producers: fill next tile into the other stage
            if (t + 1 < ntiles) {
                const int p = tid - 32;
                const int base = (t + 1) * TILE;
                #pragma unroll
                for (int k = 0; k < TILE / NPROD; k++) {
                    int i = p + k * NPROD;
                    int f = base + i;
                    if (f < F) {
                        float v  = __ldg(emb + (long)f * 16 + e);
                        float xv = __ldg(x + f);
                        s_t[cur ^ 1][0][i] = __fmul_rn(v, xv);
                        s_t[cur ^ 1][1][i] = __fmul_rn(__fmul_rn(v, v),
                                                       __fmul_rn(xv, xv));
                    }
                }
            }
        } else if (tid < 2) {
            // consumer: strictly sequential fp32 adds, f ascending
            const float* __restrict__ buf = s_t[cur][tid];
            int cnt = F - t * TILE;
            if (cnt >= TILE) {
                #pragma unroll 16
                for (int i = 0; i < TILE; i++) acc = __fadd_rn(acc, buf[i]);
            } else {
                for (int i = 0; i < cnt; i++) acc = __fadd_rn(acc, buf[i]);
            }
        }
        __syncthreads();
    }

    if (tid < 2) g_accf[tid * 16 + e] = acc;
}

// Tail: logistic + FM + 2-layer MLP + sigmoid. 1 block, 32 threads, fp32.
__global__ void tail_kernel(const float* __restrict__ w_log,   // (1,16)
                            const float* __restrict__ b_log,   // (1,)
                            const float* __restrict__ w1,      // (32,16)
                            const float* __restrict__ b1,      // (32,)
                            const float* __restrict__ w2,      // (32,32)
                            const float* __restrict__ b2,      // (32,)
                            const float* __restrict__ w_out,   // (1,49)
                            const float* __restrict__ b_out,   // (1,)
                            float* __restrict__ out) {
    __shared__ float s_h1[32];
    __shared__ float s_embf[16];
    int t = threadIdx.x;

    if (t < 16) s_embf[t] = g_accf[t];
    __syncwarp();

    float h1 = b1[t];
    #pragma unroll
    for (int e = 0; e < 16; e++) h1 = fmaf(s_embf[e], w1[t * 16 + e], h1);
    h1 = fmaxf(h1, 0.0f);
    s_h1[t] = h1;
    __syncwarp();

    float h2 = b2[t];
    #pragma unroll
    for (int k = 0; k < 32; k++) h2 = fmaf(s_h1[k], w2[t * 32 + k], h2);
    h2 = fmaxf(h2, 0.0f);

    float part = h2 * w_out[t];
    if (t < 16) {
        float ef = s_embf[t];
        float fm = 0.5f * (ef * ef - g_accf[16 + t]);
        part = fmaf(fm, w_out[32 + t], part);
    }
    if (t == 0) {
        float logit = b_log[0];
        #pragma unroll
        for (int e = 0; e < 16; e++) logit = fmaf(s_embf[e], w_log[e], logit);
        part = fmaf(logit, w_out[48], part);
        part += b_out[0];
    }

    #pragma unroll
    for (int off = 16; off > 0; off >>= 1)
        part += __shfl_down_sync(0xffffffffu, part, off);

    if (t == 0) out[0] = 1.0f / (1.0f + expf(-part));
}

extern "C" void kernel_launch(void* const* d_in, const int* in_sizes, int n_in,
                              void* d_out, int out_size) {
    const float* x     = (const float*)d_in[0];
    const float* emb   = (const float*)d_in[1];
    const float* w_log = (const float*)d_in[2];
    const float* b_log = (const float*)d_in[3];
    const float* w1    = (const float*)d_in[4];
    const float* b1    = (const float*)d_in[5];
    const float* w2    = (const float*)d_in[6];
    const float* b2    = (const float*)d_in[7];
    const float* w_out = (const float*)d_in[8];
    const float* b_out = (const float*)d_in[9];
    float* out = (float*)d_out;

    int F = in_sizes[0];   // 2,000,000

    serial_chain_kernel<<<16, 160>>>(x, emb, F);
    tail_kernel<<<1, 32>>>(w_log, b_log, w1, b1, w2, b2, w_out, b_out, out);
}

// round 6
// speedup vs baseline: 137.3770x; 10.6448x over previous
#include <cuda_runtime.h>
#include <math.h>

#define NTILES   64
#define S1_SPLIT 4
#define CHUNK    250
#define NPRODW   8
#define S2_THREADS ((1 + NPRODW) * 32)

// scratch (no allocations allowed)
__device__ double g_tilesum[NTILES][32];   // exact double tile sums per chain
__device__ float  g_sstar[NTILES][32];     // fp32 chain start value per tile
__device__ double g_cdelta[NTILES][32];    // replayed fp32 tile delta

__global__ void zero_kernel() {
    double* p = &g_tilesum[0][0];
    for (int i = threadIdx.x; i < NTILES * 32; i += blockDim.x) p[i] = 0.0;
}

// ---- stage 1: exact double sums of chain terms per tile (order-free) ----
// lane = chain: lanes 0..15 -> embf(e), 16..31 -> squ(e). Quarter-tile blocks.
__global__ void __launch_bounds__(512, 1)
stage1_kernel(const float* __restrict__ x, const float* __restrict__ emb,
              int F, int tilef) {
    __shared__ double sred[16][32];
    const int tile = blockIdx.x / S1_SPLIT;
    const int part = blockIdx.x % S1_SPLIT;
    const int tid = threadIdx.x, lane = tid & 31, warp = tid >> 5;
    const int e = lane & 15;
    const bool sq = lane >= 16;

    const long long base = (long long)tile * tilef;
    const int len = min(tilef, F - (int)base);
    const int plen = (len + S1_SPLIT - 1) / S1_SPLIT;
    const int pbeg = part * plen;
    const int pend = min(len, pbeg + plen);

    double a0 = 0, a1 = 0, a2 = 0, a3 = 0;
    for (int i0 = pbeg + warp; i0 < pend; i0 += 64) {
        #pragma unroll
        for (int k = 0; k < 4; k++) {
            int i = i0 + 16 * k;
            if (i < pend) {
                long long f = base + i;
                float v  = __ldg(emb + f * 16 + e);
                float xv = __ldg(x + f);
                float a = sq ? __fmul_rn(v, v)   : v;
                float b = sq ? __fmul_rn(xv, xv) : xv;
                double* acc = (k == 0) ? &a0 : (k == 1) ? &a1 : (k == 2) ? &a2 : &a3;
                *acc = fma((double)a, (double)b, *acc);
            }
        }
    }
    sred[warp][lane] = (a0 + a1) + (a2 + a3);
    __syncthreads();
    if (warp == 0) {
        double s = 0;
        #pragma unroll
        for (int w = 0; w < 16; w++) s += sred[w][lane];
        atomicAdd(&g_tilesum[tile][lane], s);
    }
}

// ---- stage 1.5: serial prefix over tiles -> fp32 start values ----
__global__ void prefix_kernel() {
    int c = threadIdx.x;   // 0..31 chain id
    double P = 0.0;
    for (int t = 0; t < NTILES; t++) {
        g_sstar[t][c] = (float)P;
        P += g_tilesum[t][c];
    }
}

// ---- stage 2: parallel fp32 replay of each tile from its start value ----
// Block = 1 consumer warp (32 chains, one per lane) + NPRODW producer warps
// staging (a,b) operand pairs in a double-buffered smem chunk.
__global__ void __launch_bounds__(S2_THREADS, 1)
stage2_kernel(const float* __restrict__ x, const float* __restrict__ emb,
              int F, int tilef) {
    extern __shared__ float2 s_ab[];   // [2][CHUNK][32]
    const int tile = blockIdx.x;
    const int tid = threadIdx.x, lane = tid & 31, warp = tid >> 5;
    const int e = lane & 15;
    const bool sq = lane >= 16;
    const long long base = (long long)tile * tilef;
    const int len = min(tilef, F - (int)base);
    const int nchunk = (len + CHUNK - 1) / CHUNK;

    // prologue: fill chunk 0
    if (warp > 0) {
        int cnt = min(CHUNK, len);
        for (int i = warp - 1; i < cnt; i += NPRODW) {
            long long f = base + i;
            float v  = __ldg(emb + f * 16 + e);
            float xv = __ldg(x + f);
            float a = sq ? __fmul_rn(v, v)   : v;
            float b = sq ? __fmul_rn(xv, xv) : xv;
            s_ab[i * 32 + lane] = make_float2(a, b);
        }
    }
    __syncthreads();

    float acc = g_sstar[tile][lane];

    for (int c = 0; c < nchunk; c++) {
        const int buf = c & 1;
        if (warp == 0) {
            // consumer: strictly sequential fp32 FMA chain, f ascending
            const float2* __restrict__ p = s_ab + (size_t)buf * (CHUNK * 32) + lane;
            int cnt = min(CHUNK, len - c * CHUNK);
            if (cnt == CHUNK) {
                #pragma unroll 10
                for (int i = 0; i < CHUNK; i++) {
                    float2 t = p[(size_t)i * 32];
                    acc = __fmaf_rn(t.x, t.y, acc);
                }
            } else {
                for (int i = 0; i < cnt; i++) {
                    float2 t = p[(size_t)i * 32];
                    acc = __fmaf_rn(t.x, t.y, acc);
                }
            }
        } else if (c + 1 < nchunk) {
            const int nb = (c + 1) & 1;
            const int cbase = (c + 1) * CHUNK;
            int cnt = min(CHUNK, len - cbase);
            for (int i = warp - 1; i < cnt; i += NPRODW) {
                long long f = base + cbase + i;
                float v  = __ldg(emb + f * 16 + e);
                float xv = __ldg(x + f);
                float a = sq ? __fmul_rn(v, v)   : v;
                float b = sq ? __fmul_rn(xv, xv) : xv;
                s_ab[((size_t)nb * CHUNK + i) * 32 + lane] = make_float2(a, b);
            }
        }
        __syncthreads();
    }

    if (warp == 0)
        g_cdelta[tile][lane] = (double)acc - (double)g_sstar[tile][lane];
}

// ---- stage 3: assemble chains + MLP tail. 1 block, 32 threads. ----
__global__ void tail_kernel(const float* __restrict__ w_log,   // (1,16)
                            const float* __restrict__ b_log,   // (1,)
                            const float* __restrict__ w1,      // (32,16)
                            const float* __restrict__ b1,      // (32,)
                            const float* __restrict__ w2,      // (32,32)
                            const float* __restrict__ b2,      // (32,)
                            const float* __restrict__ w_out,   // (1,49)
                            const float* __restrict__ b_out,   // (1,)
                            float* __restrict__ out) {
    __shared__ float s_acc[32];   // [0..15] embf, [16..31] squ
    __shared__ float s_h1[32];
    int t = threadIdx.x;

    double S = 0.0;
    for (int u = 0; u < NTILES; u++) S += g_cdelta[u][t];
    s_acc[t] = (float)S;
    __syncwarp();

    // h1 = relu(embf @ w1^T + b1)
    float h1 = b1[t];
    #pragma unroll
    for (int e = 0; e < 16; e++) h1 = fmaf(s_acc[e], w1[t * 16 + e], h1);
    h1 = fmaxf(h1, 0.0f);
    s_h1[t] = h1;
    __syncwarp();

    // h2 = relu(h1 @ w2^T + b2)
    float h2 = b2[t];
    #pragma unroll
    for (int k = 0; k < 32; k++) h2 = fmaf(s_h1[k], w2[t * 32 + k], h2);
    h2 = fmaxf(h2, 0.0f);

    // concat = [h2 (32), fm (16), logistic (1)] . w_out + b_out
    float part = h2 * w_out[t];
    if (t < 16) {
        float ef = s_acc[t];
        float fm = 0.5f * (ef * ef - s_acc[16 + t]);
        part = fmaf(fm, w_out[32 + t], part);
    }
    if (t == 0) {
        float logit = b_log[0];
        #pragma unroll
        for (int e = 0; e < 16; e++) logit = fmaf(s_acc[e], w_log[e], logit);
        part = fmaf(logit, w_out[48], part);
        part += b_out[0];
    }

    #pragma unroll
    for (int off = 16; off > 0; off >>= 1)
        part += __shfl_down_sync(0xffffffffu, part, off);

    if (t == 0) out[0] = 1.0f / (1.0f + expf(-part));
}

extern "C" void kernel_launch(void* const* d_in, const int* in_sizes, int n_in,
                              void* d_out, int out_size) {
    const float* x     = (const float*)d_in[0];
    const float* emb   = (const float*)d_in[1];
    const float* w_log = (const float*)d_in[2];
    const float* b_log = (const float*)d_in[3];
    const float* w1    = (const float*)d_in[4];
    const float* b1    = (const float*)d_in[5];
    const float* w2    = (const float*)d_in[6];
    const float* b2    = (const float*)d_in[7];
    const float* w_out = (const float*)d_in[8];
    const float* b_out = (const float*)d_in[9];
    float* out = (float*)d_out;

    int F = in_sizes[0];                       // 2,000,000
    int tilef = (F + NTILES - 1) / NTILES;     // 31250

    const int s2_smem = 2 * CHUNK * 32 * (int)sizeof(float2);  // 128000 B
    cudaFuncSetAttribute(stage2_kernel,
                         cudaFuncAttributeMaxDynamicSharedMemorySize, s2_smem);

    zero_kernel<<<1, 256>>>();
    stage1_kernel<<<NTILES * S1_SPLIT, 512>>>(x, emb, F, tilef);
    prefix_kernel<<<1, 32>>>();
    stage2_kernel<<<NTILES, S2_THREADS, s2_smem>>>(x, emb, F, tilef);
    tail_kernel<<<1, 32>>>(w_log, b_log, w1, b1, w2, b2, w_out, b_out, out);
}

// round 7
// speedup vs baseline: 326.9266x; 2.3798x over previous
#include <cuda_runtime.h>
#include <math.h>

#define NTILES   128
#define S1_SPLIT 4
#define CHUNK    256
#define NPRODW   8
#define PER_PROD (CHUNK / NPRODW)        // 32
#define S2_THREADS ((1 + NPRODW) * 32)   // 288

// scratch (no device allocations allowed)
__device__ double g_part[NTILES][S1_SPLIT][32];  // stage1 partial sums
__device__ float  g_sstar[NTILES][32];           // fp32 chain start per tile
__device__ double g_cdelta[NTILES][32];          // replayed fp32 tile delta

// ---- stage 1: exact double sums of chain terms per tile (order-free) ----
// lane = chain: lanes 0..15 -> embf(e), 16..31 -> squ(e).
__global__ void __launch_bounds__(512, 1)
stage1_kernel(const float* __restrict__ x, const float* __restrict__ emb,
              int F, int tilef) {
    __shared__ double sred[16][32];
    const int tile = blockIdx.x / S1_SPLIT;
    const int part = blockIdx.x % S1_SPLIT;
    const int tid = threadIdx.x, lane = tid & 31, warp = tid >> 5;
    const int e = lane & 15;
    const bool sq = lane >= 16;

    const int base = tile * tilef;
    const int len = min(tilef, F - base);
    const int plen = (len + S1_SPLIT - 1) / S1_SPLIT;
    const int pbeg = part * plen;
    const int pend = min(len, pbeg + plen);

    double a0 = 0, a1 = 0, a2 = 0, a3 = 0;
    for (int i0 = pbeg + warp; i0 < pend; i0 += 64) {
        #pragma unroll
        for (int k = 0; k < 4; k++) {
            int i = i0 + 16 * k;
            if (i < pend) {
                int f = base + i;
                float v  = __ldg(emb + (size_t)f * 16 + e);
                float xv = __ldg(x + f);
                float a = sq ? __fmul_rn(v, v)   : v;
                float b = sq ? __fmul_rn(xv, xv) : xv;
                double* acc = (k == 0) ? &a0 : (k == 1) ? &a1 : (k == 2) ? &a2 : &a3;
                *acc = fma((double)a, (double)b, *acc);
            }
        }
    }
    sred[warp][lane] = (a0 + a1) + (a2 + a3);
    __syncthreads();
    if (warp == 0) {
        double s = 0;
        #pragma unroll
        for (int w = 0; w < 16; w++) s += sred[w][lane];
        g_part[tile][part][lane] = s;
    }
}

// ---- stage 1.5: serial prefix over tiles -> fp32 start values ----
__global__ void prefix_kernel() {
    int c = threadIdx.x;   // 0..31 chain id
    double P = 0.0;
    for (int t = 0; t < NTILES; t++) {
        g_sstar[t][c] = (float)P;
        double s = 0.0;
        #pragma unroll
        for (int p = 0; p < S1_SPLIT; p++) s += g_part[t][p][c];
        P += s;
    }
}

// ---- stage 2: parallel fp32 replay of each tile from its start value ----
// Block = 1 consumer warp (32 chains, one per lane) + NPRODW producer warps
// staging (a,b) operand pairs in a double-buffered smem chunk.
__global__ void __launch_bounds__(S2_THREADS, 1)
stage2_kernel(const float* __restrict__ x, const float* __restrict__ emb,
              int F, int tilef) {
    extern __shared__ float2 s_ab[];   // [2][CHUNK][32]
    const int tile = blockIdx.x;
    const int tid = threadIdx.x, lane = tid & 31, warp = tid >> 5;
    const int e = lane & 15;
    const bool sq = lane >= 16;
    const int base = tile * tilef;
    const int len = min(tilef, F - base);
    const int nchunk = (len + CHUNK - 1) / CHUNK;

    // producer fill of chunk index c into buffer (c&1)
    auto fill = [&](int c) {
        const int cbase = c * CHUNK;
        const int cnt = min(CHUNK, len - cbase);
        float2* __restrict__ dst = s_ab + (c & 1) * (CHUNK * 32);
        const int p = (warp - 1) * 0 + (warp - 1);  // producer id 0..7
        const float* __restrict__ embp = emb + (size_t)(base + cbase) * 16 + e;
        const float* __restrict__ xp   = x + base + cbase;
        if (cnt == CHUNK) {
            #pragma unroll 8
            for (int k = 0; k < PER_PROD; k++) {
                int i = p + k * NPRODW;
                float v  = __ldg(embp + i * 16);
                float xv = __ldg(xp + i);
                float a = sq ? __fmul_rn(v, v)   : v;
                float b = sq ? __fmul_rn(xv, xv) : xv;
                dst[i * 32 + lane] = make_float2(a, b);
            }
        } else {
            for (int i = p; i < cnt; i += NPRODW) {
                float v  = __ldg(embp + i * 16);
                float xv = __ldg(xp + i);
                float a = sq ? __fmul_rn(v, v)   : v;
                float b = sq ? __fmul_rn(xv, xv) : xv;
                dst[i * 32 + lane] = make_float2(a, b);
            }
        }
    };

    if (warp > 0) fill(0);
    __syncthreads();

    float acc = g_sstar[tile][lane];

    for (int c = 0; c < nchunk; c++) {
        if (warp == 0) {
            // consumer: strictly sequential fp32 FMA chain, f ascending
            const float2* __restrict__ p = s_ab + (c & 1) * (CHUNK * 32) + lane;
            const int cnt = min(CHUNK, len - c * CHUNK);
            if (cnt == CHUNK) {
                #pragma unroll 8
                for (int i = 0; i < CHUNK; i++) {
                    float2 t = p[i * 32];
                    acc = __fmaf_rn(t.x, t.y, acc);
                }
            } else {
                for (int i = 0; i < cnt; i++) {
                    float2 t = p[i * 32];
                    acc = __fmaf_rn(t.x, t.y, acc);
                }
            }
        } else if (c + 1 < nchunk) {
            fill(c + 1);
        }
        __syncthreads();
    }

    if (warp == 0)
        g_cdelta[tile][lane] = (double)acc - (double)g_sstar[tile][lane];
}

// ---- stage 3: assemble chains + MLP tail. 1 block, 32 threads. ----
__global__ void tail_kernel(const float* __restrict__ w_log,   // (1,16)
                            const float* __restrict__ b_log,   // (1,)
                            const float* __restrict__ w1,      // (32,16)
                            const float* __restrict__ b1,      // (32,)
                            const float* __restrict__ w2,      // (32,32)
                            const float* __restrict__ b2,      // (32,)
                            const float* __restrict__ w_out,   // (1,49)
                            const float* __restrict__ b_out,   // (1,)
                            float* __restrict__ out) {
    __shared__ float s_acc[32];   // [0..15] embf, [16..31] squ
    __shared__ float s_h1[32];
    int t = threadIdx.x;

    double S = 0.0;
    #pragma unroll 8
    for (int u = 0; u < NTILES; u++) S += g_cdelta[u][t];
    s_acc[t] = (float)S;
    __syncwarp();

    float h1 = b1[t];
    #pragma unroll
    for (int e = 0; e < 16; e++) h1 = fmaf(s_acc[e], w1[t * 16 + e], h1);
    h1 = fmaxf(h1, 0.0f);
    s_h1[t] = h1;
    __syncwarp();

    float h2 = b2[t];
    #pragma unroll
    for (int k = 0; k < 32; k++) h2 = fmaf(s_h1[k], w2[t * 32 + k], h2);
    h2 = fmaxf(h2, 0.0f);

    float part = h2 * w_out[t];
    if (t < 16) {
        float ef = s_acc[t];
        float fm = 0.5f * (ef * ef - s_acc[16 + t]);
        part = fmaf(fm, w_out[32 + t], part);
    }
    if (t == 0) {
        float logit = b_log[0];
        #pragma unroll
        for (int e = 0; e < 16; e++) logit = fmaf(s_acc[e], w_log[e], logit);
        part = fmaf(logit, w_out[48], part);
        part += b_out[0];
    }

    #pragma unroll
    for (int off = 16; off > 0; off >>= 1)
        part += __shfl_down_sync(0xffffffffu, part, off);

    if (t == 0) out[0] = 1.0f / (1.0f + expf(-part));
}

extern "C" void kernel_launch(void* const* d_in, const int* in_sizes, int n_in,
                              void* d_out, int out_size) {
    const float* x     = (const float*)d_in[0];
    const float* emb   = (const float*)d_in[1];
    const float* w_log = (const float*)d_in[2];
    const float* b_log = (const float*)d_in[3];
    const float* w1    = (const float*)d_in[4];
    const float* b1    = (const float*)d_in[5];
    const float* w2    = (const float*)d_in[6];
    const float* b2    = (const float*)d_in[7];
    const float* w_out = (const float*)d_in[8];
    const float* b_out = (const float*)d_in[9];
    float* out = (float*)d_out;

    int F = in_sizes[0];                       // 2,000,000
    int tilef = (F + NTILES - 1) / NTILES;     // 15625

    const int s2_smem = 2 * CHUNK * 32 * (int)sizeof(float2);  // 131072 B
    cudaFuncSetAttribute(stage2_kernel,
                         cudaFuncAttributeMaxDynamicSharedMemorySize, s2_smem);

    stage1_kernel<<<NTILES * S1_SPLIT, 512>>>(x, emb, F, tilef);
    prefix_kernel<<<1, 32>>>();
    stage2_kernel<<<NTILES, S2_THREADS, s2_smem>>>(x, emb, F, tilef);
    tail_kernel<<<1, 32>>>(w_log, b_log, w1, b1, w2, b2, w_out, b_out, out);
}

// round 8
// speedup vs baseline: 521.4210x; 1.5949x over previous
#include <cuda_runtime.h>
#include <math.h>

#define NTILES   256
#define S1_SPLIT 2
#define CHUNK    128
#define NPRODW   8
#define PER_PROD (CHUNK / NPRODW)        // 16
#define S2_THREADS ((1 + NPRODW) * 32)   // 288
#define TPL (NTILES / 32)                // tiles per lane in scans: 8

// scratch (no device allocations allowed)
__device__ double g_part[NTILES][S1_SPLIT][32];  // stage1 partial sums
__device__ float  g_sstar[NTILES][32];           // fp32 chain start per tile
__device__ double g_cdelta[NTILES][32];          // replayed fp32 tile delta

// ---- stage 1: exact double sums of chain terms per tile (order-free) ----
// lane = chain: lanes 0..15 -> embf(e), 16..31 -> squ(e).
__global__ void __launch_bounds__(512, 1)
stage1_kernel(const float* __restrict__ x, const float* __restrict__ emb,
              int F, int tilef) {
    __shared__ double sred[16][32];
    const int tile = blockIdx.x / S1_SPLIT;
    const int part = blockIdx.x % S1_SPLIT;
    const int tid = threadIdx.x, lane = tid & 31, warp = tid >> 5;
    const int e = lane & 15;
    const bool sq = lane >= 16;

    const int base = tile * tilef;
    const int len = min(tilef, F - base);
    const int plen = (len + S1_SPLIT - 1) / S1_SPLIT;
    const int pbeg = part * plen;
    const int pend = min(len, pbeg + plen);

    double a0 = 0, a1 = 0, a2 = 0, a3 = 0;
    for (int i0 = pbeg + warp; i0 < pend; i0 += 64) {
        #pragma unroll
        for (int k = 0; k < 4; k++) {
            int i = i0 + 16 * k;
            if (i < pend) {
                int f = base + i;
                float v  = __ldg(emb + (size_t)f * 16 + e);
                float xv = __ldg(x + f);
                float a = sq ? __fmul_rn(v, v)   : v;
                float b = sq ? __fmul_rn(xv, xv) : xv;
                double* acc = (k == 0) ? &a0 : (k == 1) ? &a1 : (k == 2) ? &a2 : &a3;
                *acc = fma((double)a, (double)b, *acc);
            }
        }
    }
    sred[warp][lane] = (a0 + a1) + (a2 + a3);
    __syncthreads();
    if (warp == 0) {
        double s = 0;
        #pragma unroll
        for (int w = 0; w < 16; w++) s += sred[w][lane];
        g_part[tile][part][lane] = s;
    }
}

// ---- stage 1.5: parallel exclusive scan over tiles -> fp32 start values ----
// 32 warps, warp w owns chain w. Lane l owns tiles [l*TPL, (l+1)*TPL).
__global__ void __launch_bounds__(1024, 1) prefix_kernel() {
    const int c = threadIdx.x >> 5;   // chain 0..31
    const int lane = threadIdx.x & 31;

    double loc[TPL];
    double tot = 0.0;
    #pragma unroll
    for (int j = 0; j < TPL; j++) {
        int t = lane * TPL + j;
        double s = 0.0;
        #pragma unroll
        for (int p = 0; p < S1_SPLIT; p++) s += g_part[t][p][c];
        loc[j] = s;
        tot += s;
    }
    // inclusive warp scan of lane totals -> exclusive start for this lane
    double scan = tot;
    #pragma unroll
    for (int off = 1; off < 32; off <<= 1) {
        double v = __shfl_up_sync(0xffffffffu, scan, off);
        if (lane >= off) scan += v;
    }
    double P = scan - tot;   // exclusive prefix of this lane's segment
    #pragma unroll
    for (int j = 0; j < TPL; j++) {
        g_sstar[lane * TPL + j][c] = (float)P;
        P += loc[j];
    }
}

// ---- stage 2: parallel fp32 replay of each tile from its start value ----
// Block = 1 consumer warp (32 chains, one per lane) + NPRODW producer warps
// staging (a,b) operand pairs in a double-buffered smem chunk.
__global__ void __launch_bounds__(S2_THREADS, 2)
stage2_kernel(const float* __restrict__ x, const float* __restrict__ emb,
              int F, int tilef) {
    extern __shared__ float2 s_ab[];   // [2][CHUNK][32]
    const int tile = blockIdx.x;
    const int tid = threadIdx.x, lane = tid & 31, warp = tid >> 5;
    const int e = lane & 15;
    const bool sq = lane >= 16;
    const int base = tile * tilef;
    const int len = min(tilef, F - base);
    const int nchunk = (len + CHUNK - 1) / CHUNK;

    auto fill = [&](int c) {
        const int cbase = c * CHUNK;
        const int cnt = min(CHUNK, len - cbase);
        float2* __restrict__ dst = s_ab + (c & 1) * (CHUNK * 32);
        const int p = warp - 1;  // producer id 0..7
        const float* __restrict__ embp = emb + (size_t)(base + cbase) * 16 + e;
        const float* __restrict__ xp   = x + base + cbase;
        if (cnt == CHUNK) {
            #pragma unroll
            for (int k = 0; k < PER_PROD; k++) {
                int i = p + k * NPRODW;
                float v  = __ldg(embp + i * 16);
                float xv = __ldg(xp + i);
                float a = sq ? __fmul_rn(v, v)   : v;
                float b = sq ? __fmul_rn(xv, xv) : xv;
                dst[i * 32 + lane] = make_float2(a, b);
            }
        } else {
            for (int i = p; i < cnt; i += NPRODW) {
                float v  = __ldg(embp + i * 16);
                float xv = __ldg(xp + i);
                float a = sq ? __fmul_rn(v, v)   : v;
                float b = sq ? __fmul_rn(xv, xv) : xv;
                dst[i * 32 + lane] = make_float2(a, b);
            }
        }
    };

    if (warp > 0) fill(0);
    __syncthreads();

    float acc = g_sstar[tile][lane];

    for (int c = 0; c < nchunk; c++) {
        if (warp == 0) {
            // consumer: strictly sequential fp32 FMA chain, f ascending
            const float2* __restrict__ p = s_ab + (c & 1) * (CHUNK * 32) + lane;
            const int cnt = min(CHUNK, len - c * CHUNK);
            if (cnt == CHUNK) {
                #pragma unroll 8
                for (int i = 0; i < CHUNK; i++) {
                    float2 t = p[i * 32];
                    acc = __fmaf_rn(t.x, t.y, acc);
                }
            } else {
                for (int i = 0; i < cnt; i++) {
                    float2 t = p[i * 32];
                    acc = __fmaf_rn(t.x, t.y, acc);
                }
            }
        } else if (c + 1 < nchunk) {
            fill(c + 1);
        }
        __syncthreads();
    }

    if (warp == 0)
        g_cdelta[tile][lane] = (double)acc - (double)g_sstar[tile][lane];
}

// ---- stage 3: parallel delta reduction + MLP tail. 1 block, 1024 threads. ----
__global__ void __launch_bounds__(1024, 1)
tail_kernel(const float* __restrict__ w_log,   // (1,16)
            const float* __restrict__ b_log,   // (1,)
            const float* __restrict__ w1,      // (32,16)
            const float* __restrict__ b1,      // (32,)
            const float* __restrict__ w2,      // (32,32)
            const float* __restrict__ b2,      // (32,)
            const float* __restrict__ w_out,   // (1,49)
            const float* __restrict__ b_out,   // (1,)
            float* __restrict__ out) {
    __shared__ float s_acc[32];   // [0..15] embf, [16..31] squ
    __shared__ float s_h1[32];
    const int c = threadIdx.x >> 5;   // chain
    const int lane = threadIdx.x & 31;

    // warp c reduces the 256 tile deltas of chain c
    double S = 0.0;
    #pragma unroll
    for (int j = 0; j < TPL; j++) S += g_cdelta[lane * TPL + j][c];
    #pragma unroll
    for (int off = 16; off > 0; off >>= 1)
        S += __shfl_down_sync(0xffffffffu, S, off);
    if (lane == 0) s_acc[c] = (float)S;
    __syncthreads();

    if (threadIdx.x >= 32) return;
    const int t = threadIdx.x;

    float h1 = b1[t];
    #pragma unroll
    for (int e = 0; e < 16; e++) h1 = fmaf(s_acc[e], w1[t * 16 + e], h1);
    h1 = fmaxf(h1, 0.0f);
    s_h1[t] = h1;
    __syncwarp();

    float h2 = b2[t];
    #pragma unroll
    for (int k = 0; k < 32; k++) h2 = fmaf(s_h1[k], w2[t * 32 + k], h2);
    h2 = fmaxf(h2, 0.0f);

    float part = h2 * w_out[t];
    if (t < 16) {
        float ef = s_acc[t];
        float fm = 0.5f * (ef * ef - s_acc[16 + t]);
        part = fmaf(fm, w_out[32 + t], part);
    }
    if (t == 0) {
        float logit = b_log[0];
        #pragma unroll
        for (int e = 0; e < 16; e++) logit = fmaf(s_acc[e], w_log[e], logit);
        part = fmaf(logit, w_out[48], part);
        part += b_out[0];
    }

    #pragma unroll
    for (int off = 16; off > 0; off >>= 1)
        part += __shfl_down_sync(0xffffffffu, part, off);

    if (t == 0) out[0] = 1.0f / (1.0f + expf(-part));
}

extern "C" void kernel_launch(void* const* d_in, const int* in_sizes, int n_in,
                              void* d_out, int out_size) {
    const float* x     = (const float*)d_in[0];
    const float* emb   = (const float*)d_in[1];
    const float* w_log = (const float*)d_in[2];
    const float* b_log = (const float*)d_in[3];
    const float* w1    = (const float*)d_in[4];
    const float* b1    = (const float*)d_in[5];
    const float* w2    = (const float*)d_in[6];
    const float* b2    = (const float*)d_in[7];
    const float* w_out = (const float*)d_in[8];
    const float* b_out = (const float*)d_in[9];
    float* out = (float*)d_out;

    int F = in_sizes[0];                       // 2,000,000
    int tilef = (F + NTILES - 1) / NTILES;     // 7813

    const int s2_smem = 2 * CHUNK * 32 * (int)sizeof(float2);  // 65536 B
    cudaFuncSetAttribute(stage2_kernel,
                         cudaFuncAttributeMaxDynamicSharedMemorySize, s2_smem);

    stage1_kernel<<<NTILES * S1_SPLIT, 512>>>(x, emb, F, tilef);
    prefix_kernel<<<1, 1024>>>();
    stage2_kernel<<<NTILES, S2_THREADS, s2_smem>>>(x, emb, F, tilef);
    tail_kernel<<<1, 1024>>>(w_log, b_log, w1, b1, w2, b2, w_out, b_out, out);
}

// round 9
// speedup vs baseline: 533.4709x; 1.0231x over previous
#include <cuda_runtime.h>
#include <math.h>

#define NTILES   444
#define CHUNK    128
#define NPRODW   8
#define PER_PROD (CHUNK / NPRODW)        // 16
#define S2_THREADS ((1 + NPRODW) * 32)   // 288
#define TPL 14                           // ceil(444/32) tiles per lane in scan

// scratch (no device allocations allowed)
__device__ double g_part[NTILES][32];    // stage1 tile sums (double-combined fp32)
__device__ float  g_sstar[NTILES][32];   // fp32 chain start per tile
__device__ double g_cdelta[NTILES][32];  // replayed fp32 tile delta
__device__ unsigned int g_cnt1 = 0;      // last-block counters (reset each run)
__device__ unsigned int g_cnt2 = 0;

// ---- stage 1: fp32 split-accumulator tile sums + fused prefix scan ----
// lane = chain: lanes 0..15 -> embf(e), 16..31 -> squ(e). One block per tile.
__global__ void __launch_bounds__(512, 1)
stage1_kernel(const float* __restrict__ x, const float* __restrict__ emb,
              int F, int tilef) {
    __shared__ double sred[16][32];
    __shared__ unsigned int s_last;
    const int tile = blockIdx.x;
    const int tid = threadIdx.x, lane = tid & 31, warp = tid >> 5;
    const int e = lane & 15;
    const bool sq = lane >= 16;

    const int base = tile * tilef;
    const int len = min(tilef, F - base);

    float a0 = 0.f, a1 = 0.f, a2 = 0.f, a3 = 0.f;
    for (int i0 = warp; i0 < len; i0 += 64) {
        #pragma unroll
        for (int k = 0; k < 4; k++) {
            int i = i0 + 16 * k;
            if (i < len) {
                int f = base + i;
                float v  = __ldg(emb + (size_t)f * 16 + e);
                float xv = __ldg(x + f);
                float a = sq ? __fmul_rn(v, v)   : v;
                float b = sq ? __fmul_rn(xv, xv) : xv;
                float* acc = (k == 0) ? &a0 : (k == 1) ? &a1 : (k == 2) ? &a2 : &a3;
                *acc = __fmaf_rn(a, b, *acc);
            }
        }
    }
    sred[warp][lane] = ((double)a0 + (double)a1) + ((double)a2 + (double)a3);
    __syncthreads();
    if (warp == 0) {
        double s = 0;
        #pragma unroll
        for (int w = 0; w < 16; w++) s += sred[w][lane];
        g_part[tile][lane] = s;
    }

    // ---- last block runs the exclusive prefix scan over tiles ----
    __syncthreads();
    if (tid == 0) {
        __threadfence();
        unsigned int r = atomicAdd(&g_cnt1, 1u);
        s_last = (r == (unsigned)gridDim.x - 1u) ? 1u : 0u;
    }
    __syncthreads();
    if (!s_last) return;
    __threadfence();

    // 16 warps; warp w scans chains w and w+16. Lane l owns tiles [l*14, l*14+14).
    if (warp < 16) {
        #pragma unroll
        for (int half = 0; half < 2; half++) {
            const int c = warp + 16 * half;
            double loc[TPL];
            double tot = 0.0;
            #pragma unroll
            for (int j = 0; j < TPL; j++) {
                int t = lane * TPL + j;
                double s = (t < NTILES) ? g_part[t][c] : 0.0;
                loc[j] = s;
                tot += s;
            }
            double scan = tot;
            #pragma unroll
            for (int off = 1; off < 32; off <<= 1) {
                double v = __shfl_up_sync(0xffffffffu, scan, off);
                if (lane >= off) scan += v;
            }
            double P = scan - tot;   // exclusive prefix for this lane's segment
            #pragma unroll
            for (int j = 0; j < TPL; j++) {
                int t = lane * TPL + j;
                if (t < NTILES) g_sstar[t][c] = (float)P;
                P += loc[j];
            }
        }
    }
    if (tid == 0) g_cnt1 = 0;   // reset for next graph replay
}

// ---- stage 2: parallel fp32 replay of each tile + fused tail/MLP ----
__global__ void __launch_bounds__(S2_THREADS, 3)
stage2_kernel(const float* __restrict__ x, const float* __restrict__ emb,
              int F, int tilef,
              const float* __restrict__ w_log, const float* __restrict__ b_log,
              const float* __restrict__ w1,    const float* __restrict__ b1,
              const float* __restrict__ w2,    const float* __restrict__ b2,
              const float* __restrict__ w_out, const float* __restrict__ b_out,
              float* __restrict__ out) {
    extern __shared__ float2 s_ab[];   // [2][CHUNK][32]
    __shared__ unsigned int s_last;
    __shared__ double sred2[32][8];
    __shared__ float s_acc[32];
    __shared__ float s_h1[32];

    const int tile = blockIdx.x;
    const int tid = threadIdx.x, lane = tid & 31, warp = tid >> 5;
    const int e = lane & 15;
    const bool sq = lane >= 16;
    const int base = tile * tilef;
    const int len = min(tilef, F - base);
    const int nchunk = (len + CHUNK - 1) / CHUNK;

    auto fill = [&](int c) {
        const int cbase = c * CHUNK;
        const int cnt = min(CHUNK, len - cbase);
        float2* __restrict__ dst = s_ab + (c & 1) * (CHUNK * 32);
        const int p = warp - 1;  // producer id 0..7
        const float* __restrict__ embp = emb + (size_t)(base + cbase) * 16 + e;
        const float* __restrict__ xp   = x + base + cbase;
        if (cnt == CHUNK) {
            #pragma unroll
            for (int k = 0; k < PER_PROD; k++) {
                int i = p + k * NPRODW;
                float v  = __ldg(embp + i * 16);
                float xv = __ldg(xp + i);
                float a = sq ? __fmul_rn(v, v)   : v;
                float b = sq ? __fmul_rn(xv, xv) : xv;
                dst[i * 32 + lane] = make_float2(a, b);
            }
        } else {
            for (int i = p; i < cnt; i += NPRODW) {
                float v  = __ldg(embp + i * 16);
                float xv = __ldg(xp + i);
                float a = sq ? __fmul_rn(v, v)   : v;
                float b = sq ? __fmul_rn(xv, xv) : xv;
                dst[i * 32 + lane] = make_float2(a, b);
            }
        }
    };

    if (warp > 0) fill(0);
    __syncthreads();

    float acc = g_sstar[tile][lane];

    for (int c = 0; c < nchunk; c++) {
        if (warp == 0) {
            // consumer: strictly sequential fp32 FMA chain, f ascending
            const float2* __restrict__ p = s_ab + (c & 1) * (CHUNK * 32) + lane;
            const int cnt = min(CHUNK, len - c * CHUNK);
            if (cnt == CHUNK) {
                #pragma unroll 8
                for (int i = 0; i < CHUNK; i++) {
                    float2 t = p[i * 32];
                    acc = __fmaf_rn(t.x, t.y, acc);
                }
            } else {
                for (int i = 0; i < cnt; i++) {
                    float2 t = p[i * 32];
                    acc = __fmaf_rn(t.x, t.y, acc);
                }
            }
        } else if (c + 1 < nchunk) {
            fill(c + 1);
        }
        __syncthreads();
    }

    if (warp == 0)
        g_cdelta[tile][lane] = (double)acc - (double)g_sstar[tile][lane];

    // ---- last block runs the delta reduction + MLP tail ----
    __syncthreads();
    if (tid == 0) {
        __threadfence();
        unsigned int r = atomicAdd(&g_cnt2, 1u);
        s_last = (r == (unsigned)gridDim.x - 1u) ? 1u : 0u;
    }
    __syncthreads();
    if (!s_last) return;
    __threadfence();

    // 256 threads: thread (c*8 + j) sums deltas t = j, j+8, ... for chain c
    if (tid < 256) {
        const int c = tid >> 3, j = tid & 7;
        double S0 = 0.0, S1 = 0.0;
        for (int t = j; t < NTILES; t += 16) S0 += g_cdelta[t][c];
        for (int t = j + 8; t < NTILES; t += 16) S1 += g_cdelta[t][c];
        sred2[c][j] = S0 + S1;
    }
    __syncthreads();
    if (tid < 32) {
        double S = 0.0;
        #pragma unroll
        for (int j = 0; j < 8; j++) S += sred2[tid][j];
        s_acc[tid] = (float)S;
    }
    __syncthreads();

    if (tid < 32) {
        const int t = tid;
        float h1 = b1[t];
        #pragma unroll
        for (int k = 0; k < 16; k++) h1 = fmaf(s_acc[k], w1[t * 16 + k], h1);
        h1 = fmaxf(h1, 0.0f);
        s_h1[t] = h1;
        __syncwarp();

        float h2 = b2[t];
        #pragma unroll
        for (int k = 0; k < 32; k++) h2 = fmaf(s_h1[k], w2[t * 32 + k], h2);
        h2 = fmaxf(h2, 0.0f);

        float part = h2 * w_out[t];
        if (t < 16) {
            float ef = s_acc[t];
            float fm = 0.5f * (ef * ef - s_acc[16 + t]);
            part = fmaf(fm, w_out[32 + t], part);
        }
        if (t == 0) {
            float logit = b_log[0];
            #pragma unroll
            for (int k = 0; k < 16; k++) logit = fmaf(s_acc[k], w_log[k], logit);
            part = fmaf(logit, w_out[48], part);
            part += b_out[0];
        }

        #pragma unroll
        for (int off = 16; off > 0; off >>= 1)
            part += __shfl_down_sync(0xffffffffu, part, off);

        if (t == 0) {
            out[0] = 1.0f / (1.0f + expf(-part));
            g_cnt2 = 0;   // reset for next graph replay
        }
    }
}

extern "C" void kernel_launch(void* const* d_in, const int* in_sizes, int n_in,
                              void* d_out, int out_size) {
    const float* x     = (const float*)d_in[0];
    const float* emb   = (const float*)d_in[1];
    const float* w_log = (const float*)d_in[2];
    const float* b_log = (const float*)d_in[3];
    const float* w1    = (const float*)d_in[4];
    const float* b1    = (const float*)d_in[5];
    const float* w2    = (const float*)d_in[6];
    const float* b2    = (const float*)d_in[7];
    const float* w_out = (const float*)d_in[8];
    const float* b_out = (const float*)d_in[9];
    float* out = (float*)d_out;

    int F = in_sizes[0];                       // 2,000,000
    int tilef = (F + NTILES - 1) / NTILES;     // 4505

    const int s2_smem = 2 * CHUNK * 32 * (int)sizeof(float2);  // 65536 B
    static int configured = 0;
    if (!configured) {
        cudaFuncSetAttribute(stage2_kernel,
                             cudaFuncAttributeMaxDynamicSharedMemorySize, s2_smem);
        configured = 1;
    }

    stage1_kernel<<<NTILES, 512>>>(x, emb, F, tilef);
    stage2_kernel<<<NTILES, S2_THREADS, s2_smem>>>(x, emb, F, tilef,
                                                   w_log, b_log, w1, b1,
                                                   w2, b2, w_out, b_out, out);
}

// round 10
// speedup vs baseline: 887.3590x; 1.6634x over previous
#include <cuda_runtime.h>
#include <math.h>

#define NTILES   444
#define CHUNK    256
#define S2_THREADS 320                    // warp0 consumer, 1..8 row prod, 9 x prod
#define TPL 14                            // ceil(444/32) tiles per lane in scan
#define SA_PITCH 33                       // smem floats per row (conflict-free)
#define SA_BUF   (CHUNK * SA_PITCH)       // one stage-2 buffer, floats

// scratch (no device allocations allowed)
__device__ double g_part[NTILES][32];     // stage1 tile sums
__device__ float  g_sstar[NTILES][32];    // fp32 chain start per tile
__device__ double g_cdelta[NTILES][32];   // replayed fp32 tile delta
__device__ unsigned int g_cnt1 = 0;       // last-block counters (reset each run)
__device__ unsigned int g_cnt2 = 0;

// ---- stage 1: float4-coalesced fp32 tile sums + fused prefix scan ----
__global__ void __launch_bounds__(512, 1)
stage1_kernel(const float* __restrict__ x, const float* __restrict__ emb,
              int F, int tilef) {
    __shared__ float sred[16][32];
    __shared__ unsigned int s_last;
    const int tile = blockIdx.x;
    const int tid = threadIdx.x, lane = tid & 31, warp = tid >> 5;

    const int base = tile * tilef;
    const int len = min(tilef, F - base);
    const int n4 = len * 4;

    // thread owns column group (tid & 3); stride 512 keeps it fixed
    float ae0 = 0.f, ae1 = 0.f, ae2 = 0.f, ae3 = 0.f;
    float as0 = 0.f, as1 = 0.f, as2 = 0.f, as3 = 0.f;
    const float4* __restrict__ emb4 =
        (const float4*)(emb + (size_t)base * 16);

    #pragma unroll 4
    for (int j = tid; j < n4; j += 512) {
        float4 v = __ldg(emb4 + j);
        float xv = __ldg(x + base + (j >> 2));
        float x2 = xv * xv;
        ae0 = __fmaf_rn(v.x, xv, ae0);
        ae1 = __fmaf_rn(v.y, xv, ae1);
        ae2 = __fmaf_rn(v.z, xv, ae2);
        ae3 = __fmaf_rn(v.w, xv, ae3);
        as0 = __fmaf_rn(v.x * v.x, x2, as0);
        as1 = __fmaf_rn(v.y * v.y, x2, as1);
        as2 = __fmaf_rn(v.z * v.z, x2, as2);
        as3 = __fmaf_rn(v.w * v.w, x2, as3);
    }

    // reduce lanes with same (lane & 3)
    #pragma unroll
    for (int off = 16; off >= 4; off >>= 1) {
        ae0 += __shfl_down_sync(0xffffffffu, ae0, off);
        ae1 += __shfl_down_sync(0xffffffffu, ae1, off);
        ae2 += __shfl_down_sync(0xffffffffu, ae2, off);
        ae3 += __shfl_down_sync(0xffffffffu, ae3, off);
        as0 += __shfl_down_sync(0xffffffffu, as0, off);
        as1 += __shfl_down_sync(0xffffffffu, as1, off);
        as2 += __shfl_down_sync(0xffffffffu, as2, off);
        as3 += __shfl_down_sync(0xffffffffu, as3, off);
    }
    if (lane < 4) {
        int c0 = lane * 4;   // columns c0..c0+3
        sred[warp][c0 + 0] = ae0;  sred[warp][c0 + 1] = ae1;
        sred[warp][c0 + 2] = ae2;  sred[warp][c0 + 3] = ae3;
        sred[warp][16 + c0 + 0] = as0;  sred[warp][16 + c0 + 1] = as1;
        sred[warp][16 + c0 + 2] = as2;  sred[warp][16 + c0 + 3] = as3;
    }
    __syncthreads();
    if (warp == 0) {
        double s = 0;
        #pragma unroll
        for (int w = 0; w < 16; w++) s += (double)sred[w][lane];
        g_part[tile][lane] = s;
    }

    // ---- last block: exclusive prefix scan over tiles ----
    __syncthreads();
    if (tid == 0) {
        __threadfence();
        unsigned int r = atomicAdd(&g_cnt1, 1u);
        s_last = (r == (unsigned)gridDim.x - 1u) ? 1u : 0u;
    }
    __syncthreads();
    if (!s_last) return;
    __threadfence();

    if (warp < 16) {
        #pragma unroll
        for (int half = 0; half < 2; half++) {
            const int c = warp + 16 * half;
            double loc[TPL];
            double tot = 0.0;
            #pragma unroll
            for (int j = 0; j < TPL; j++) {
                int t = lane * TPL + j;
                double s = (t < NTILES) ? g_part[t][c] : 0.0;
                loc[j] = s;
                tot += s;
            }
            double scan = tot;
            #pragma unroll
            for (int off = 1; off < 32; off <<= 1) {
                double v = __shfl_up_sync(0xffffffffu, scan, off);
                if (lane >= off) scan += v;
            }
            double P = scan - tot;
            #pragma unroll
            for (int j = 0; j < TPL; j++) {
                int t = lane * TPL + j;
                if (t < NTILES) g_sstar[t][c] = (float)P;
                P += loc[j];
            }
        }
    }
    if (tid == 0) g_cnt1 = 0;
}

// ---- stage 2: replay each tile's fp32 chain + fused tail/MLP ----
__global__ void __launch_bounds__(S2_THREADS, 3)
stage2_kernel(const float* __restrict__ x, const float* __restrict__ emb,
              int F, int tilef,
              const float* __restrict__ w_log, const float* __restrict__ b_log,
              const float* __restrict__ w1,    const float* __restrict__ b1,
              const float* __restrict__ w2,    const float* __restrict__ b2,
              const float* __restrict__ w_out, const float* __restrict__ b_out,
              float* __restrict__ out) {
    extern __shared__ float smem_raw[];
    float*  s_a = smem_raw;                          // [2][CHUNK][SA_PITCH]
    float2* s_x = (float2*)(smem_raw + 2 * SA_BUF);  // [2][CHUNK]
    __shared__ unsigned int s_last;
    __shared__ double sred2[32][8];
    __shared__ float s_acc[32];
    __shared__ float s_h1[32];

    const int tile = blockIdx.x;
    const int tid = threadIdx.x, lane = tid & 31, warp = tid >> 5;
    const int base = tile * tilef;
    const int len = min(tilef, F - base);
    const int nchunk = (len + CHUNK - 1) / CHUNK;
    const bool lo = lane < 16;

    auto fill = [&](int c) {
        const int cbase = c * CHUNK;
        const int cnt = min(CHUNK, len - cbase);
        const int buf = c & 1;
        if (warp >= 1 && warp <= 8) {
            float* sa = s_a + buf * SA_BUF;
            const float4* __restrict__ emb4 =
                (const float4*)(emb + (size_t)(base + cbase) * 16);
            const int pt = (warp - 1) * 32 + lane;
            const int ntask = cnt * 4;
            #pragma unroll
            for (int k = 0; k < 4; k++) {
                int task = pt + k * 256;
                if (task < ntask) {
                    int r = task >> 2, g = task & 3;
                    float4 v = __ldg(emb4 + task);
                    float* d = sa + r * SA_PITCH + g * 4;
                    d[0] = v.x;  d[1] = v.y;  d[2] = v.z;  d[3] = v.w;
                    d[16] = __fmul_rn(v.x, v.x);
                    d[17] = __fmul_rn(v.y, v.y);
                    d[18] = __fmul_rn(v.z, v.z);
                    d[19] = __fmul_rn(v.w, v.w);
                }
            }
        } else if (warp == 9) {
            float2* sx = s_x + buf * CHUNK;
            #pragma unroll
            for (int k = 0; k < CHUNK / 32; k++) {
                int i = lane + k * 32;
                if (i < cnt) {
                    float xv = __ldg(x + base + cbase + i);
                    sx[i] = make_float2(xv, __fmul_rn(xv, xv));
                }
            }
        }
    };

    if (warp > 0) fill(0);
    __syncthreads();

    float acc = g_sstar[tile][lane];

    for (int c = 0; c < nchunk; c++) {
        if (warp == 0) {
            // consumer: strictly sequential fp32 FMA chain, f ascending
            const float*  sa = s_a + (c & 1) * SA_BUF + lane;
            const float2* sx = s_x + (c & 1) * CHUNK;
            const int cnt = min(CHUNK, len - c * CHUNK);
            if (cnt == CHUNK) {
                #pragma unroll 8
                for (int i = 0; i < CHUNK; i++) {
                    float a = sa[i * SA_PITCH];
                    float2 b2 = sx[i];
                    float b = lo ? b2.x : b2.y;
                    acc = __fmaf_rn(a, b, acc);
                }
            } else {
                for (int i = 0; i < cnt; i++) {
                    float a = sa[i * SA_PITCH];
                    float2 b2 = sx[i];
                    float b = lo ? b2.x : b2.y;
                    acc = __fmaf_rn(a, b, acc);
                }
            }
        } else if (c + 1 < nchunk) {
            fill(c + 1);
        }
        __syncthreads();
    }

    if (warp == 0)
        g_cdelta[tile][lane] = (double)acc - (double)g_sstar[tile][lane];

    // ---- last block: delta reduction + MLP tail ----
    __syncthreads();
    if (tid == 0) {
        __threadfence();
        unsigned int r = atomicAdd(&g_cnt2, 1u);
        s_last = (r == (unsigned)gridDim.x - 1u) ? 1u : 0u;
    }
    __syncthreads();
    if (!s_last) return;
    __threadfence();

    if (tid < 256) {
        const int c = tid >> 3, j = tid & 7;
        double S0 = 0.0, S1 = 0.0;
        for (int t = j; t < NTILES; t += 16) S0 += g_cdelta[t][c];
        for (int t = j + 8; t < NTILES; t += 16) S1 += g_cdelta[t][c];
        sred2[c][j] = S0 + S1;
    }
    __syncthreads();
    if (tid < 32) {
        double S = 0.0;
        #pragma unroll
        for (int j = 0; j < 8; j++) S += sred2[tid][j];
        s_acc[tid] = (float)S;
    }
    __syncthreads();

    if (tid < 32) {
        const int t = tid;
        float h1 = b1[t];
        #pragma unroll
        for (int k = 0; k < 16; k++) h1 = fmaf(s_acc[k], w1[t * 16 + k], h1);
        h1 = fmaxf(h1, 0.0f);
        s_h1[t] = h1;
        __syncwarp();

        float h2 = b2[t];
        #pragma unroll
        for (int k = 0; k < 32; k++) h2 = fmaf(s_h1[k], w2[t * 32 + k], h2);
        h2 = fmaxf(h2, 0.0f);

        float part = h2 * w_out[t];
        if (t < 16) {
            float ef = s_acc[t];
            float fm = 0.5f * (ef * ef - s_acc[16 + t]);
            part = fmaf(fm, w_out[32 + t], part);
        }
        if (t == 0) {
            float logit = b_log[0];
            #pragma unroll
            for (int k = 0; k < 16; k++) logit = fmaf(s_acc[k], w_log[k], logit);
            part = fmaf(logit, w_out[48], part);
            part += b_out[0];
        }

        #pragma unroll
        for (int off = 16; off > 0; off >>= 1)
            part += __shfl_down_sync(0xffffffffu, part, off);

        if (t == 0) {
            out[0] = 1.0f / (1.0f + expf(-part));
            g_cnt2 = 0;
        }
    }
}

extern "C" void kernel_launch(void* const* d_in, const int* in_sizes, int n_in,
                              void* d_out, int out_size) {
    const float* x     = (const float*)d_in[0];
    const float* emb   = (const float*)d_in[1];
    const float* w_log = (const float*)d_in[2];
    const float* b_log = (const float*)d_in[3];
    const float* w1    = (const float*)d_in[4];
    const float* b1    = (const float*)d_in[5];
    const float* w2    = (const float*)d_in[6];
    const float* b2    = (const float*)d_in[7];
    const float* w_out = (const float*)d_in[8];
    const float* b_out = (const float*)d_in[9];
    float* out = (float*)d_out;

    int F = in_sizes[0];                       // 2,000,000
    int tilef = (F + NTILES - 1) / NTILES;     // 4505

    const int s2_smem = (2 * SA_BUF) * 4 + 2 * CHUNK * 8;  // 71680 B
    static int configured = 0;
    if (!configured) {
        cudaFuncSetAttribute(stage2_kernel,
                             cudaFuncAttributeMaxDynamicSharedMemorySize, s2_smem);
        configured = 1;
    }

    stage1_kernel<<<NTILES, 512>>>(x, emb, F, tilef);
    stage2_kernel<<<NTILES, S2_THREADS, s2_smem>>>(x, emb, F, tilef,
                                                   w_log, b_log, w1, b1,
                                                   w2, b2, w_out, b_out, out);
}